// round 5
// baseline (speedup 1.0000x reference)
#include <cuda_runtime.h>
#include <cuda_bf16.h>
#include <cstdint>

typedef __nv_bfloat16 bf16;
constexpr int SEQ = 1024, BATCH = 8, DM = 1024, NH = 16, HD = 64, FF = 4096;
constexpr int SB = SEQ * BATCH;
constexpr float EPS = 1e-5f;

// ---------------- scratch (device globals; no allocation allowed) ----------
__device__ float g_qkv[(size_t)SB * 3 * DM];
__device__ float g_ctx[(size_t)SB * DM];
__device__ float g_x[(size_t)SB * DM];
__device__ float g_tmp[(size_t)SB * DM];

__device__ bf16 g_srcH[(size_t)SB * DM],  g_srcL[(size_t)SB * DM];
__device__ bf16 g_wiH[(size_t)3 * DM * DM], g_wiL[(size_t)3 * DM * DM];
__device__ bf16 g_owH[(size_t)DM * DM],   g_owL[(size_t)DM * DM];
__device__ bf16 g_w1H[(size_t)FF * DM],   g_w1L[(size_t)FF * DM];
__device__ bf16 g_w2H[(size_t)DM * FF],   g_w2L[(size_t)DM * FF];
__device__ bf16 g_qH[(size_t)BATCH*NH*SEQ*HD], g_qL[(size_t)BATCH*NH*SEQ*HD];
__device__ bf16 g_kH[(size_t)BATCH*NH*SEQ*HD], g_kL[(size_t)BATCH*NH*SEQ*HD];
__device__ bf16 g_vtH[(size_t)BATCH*NH*HD*SEQ], g_vtL[(size_t)BATCH*NH*HD*SEQ];
__device__ bf16 g_ctxH[(size_t)SB * DM],  g_ctxL[(size_t)SB * DM];
__device__ bf16 g_xH[(size_t)SB * DM],    g_xL[(size_t)SB * DM];
__device__ bf16 g_h1H[(size_t)SB * FF],   g_h1L[(size_t)SB * FF];

// ---------------- helpers ---------------------------------------------------
__device__ __forceinline__ uint32_t smem_u32(const void* p) {
    uint32_t a;
    asm("{ .reg .u64 t; cvta.to.shared.u64 t, %1; cvt.u32.u64 %0, t; }" : "=r"(a) : "l"(p));
    return a;
}
__device__ __forceinline__ void cp16(uint32_t saddr, const void* gaddr) {
    asm volatile("cp.async.cg.shared.global [%0], [%1], 16;" :: "r"(saddr), "l"(gaddr));
}
__device__ __forceinline__ void cp_commit() { asm volatile("cp.async.commit_group;"); }
__device__ __forceinline__ void cp_wait1()  { asm volatile("cp.async.wait_group 1;"); }
__device__ __forceinline__ void cp_wait0()  { asm volatile("cp.async.wait_group 0;"); }
__device__ __forceinline__ void ldm_x4(uint32_t& r0, uint32_t& r1, uint32_t& r2, uint32_t& r3,
                                       uint32_t addr) {
    asm volatile("ldmatrix.sync.aligned.m8n8.x4.shared.b16 {%0,%1,%2,%3}, [%4];"
                 : "=r"(r0), "=r"(r1), "=r"(r2), "=r"(r3) : "r"(addr));
}
__device__ __forceinline__ void mma16816(float* c, const uint32_t* a, uint32_t b0, uint32_t b1) {
    asm volatile("mma.sync.aligned.m16n8k16.row.col.f32.bf16.bf16.f32 "
                 "{%0,%1,%2,%3}, {%4,%5,%6,%7}, {%8,%9}, {%0,%1,%2,%3};"
                 : "+f"(c[0]), "+f"(c[1]), "+f"(c[2]), "+f"(c[3])
                 : "r"(a[0]), "r"(a[1]), "r"(a[2]), "r"(a[3]), "r"(b0), "r"(b1));
}
__device__ __forceinline__ void split_hl(float x, bf16& h, bf16& l) {
    h = __float2bfloat16(x);
    l = __float2bfloat16(x - __bfloat162float(h));
}
__device__ __forceinline__ void pksplit(uint32_t& h, uint32_t& l, float a, float b) {
    bf16 ha, la, hb, lb;
    split_hl(a, ha, la); split_hl(b, hb, lb);
    __nv_bfloat162 th = __halves2bfloat162(ha, hb);
    __nv_bfloat162 tl = __halves2bfloat162(la, lb);
    h = *reinterpret_cast<uint32_t*>(&th);
    l = *reinterpret_cast<uint32_t*>(&tl);
}
__device__ __forceinline__ uint32_t pk2(float a, float b) {
    __nv_bfloat162 t = __halves2bfloat162(__float2bfloat16(a), __float2bfloat16(b));
    return *reinterpret_cast<uint32_t*>(&t);
}

// ---------------------------------------------------------------------------
// bf16 HMMA GEMM with 3-segment split accumulation (as R4) + optional
// bf16 hi/lo split output (CsH/CsL) instead of fp32 C.
// ---------------------------------------------------------------------------
template<int BN>
__global__ __launch_bounds__(256, 1)
void gemm_mma(const bf16* __restrict__ Ah, const bf16* __restrict__ Al, int lda, long sA,
              const bf16* __restrict__ Bh, const bf16* __restrict__ Bl, int ldb, long sB,
              const float* __restrict__ bias, const float* __restrict__ resid,
              float* __restrict__ C, bf16* __restrict__ CsH, bf16* __restrict__ CsL,
              int ldc, long sCb, long sCh, int Hdim, int K, int relu)
{
    extern __shared__ char smem[];
    const uint32_t sbase = smem_u32(smem);
    constexpr int ASTG = 128 * 128;
    constexpr int BSTG = BN * 128;
    const uint32_t aS = sbase;
    const uint32_t bS = sbase + 2 * ASTG;
    constexpr int NI = BN / 32;

    const int tid = threadIdx.x, wid = tid >> 5, lane = tid & 31;
    const int wm = wid >> 2, wn = wid & 3;

    if (gridDim.z > 1) {
        long z = blockIdx.z;
        Ah += z * sA; Al += z * sA;
        Bh += z * sB; Bl += z * sB;
        long co = (z / Hdim) * sCb + (z % Hdim) * sCh;
        if (C) C += co;
    }
    const long m0 = (long)blockIdx.y * 128;
    const long n0 = (long)blockIdx.x * BN;

    const int tps = K >> 6;
    const int nt  = 3 * tps;

    float acc[4][NI][4];
#pragma unroll
    for (int i = 0; i < 4; i++)
#pragma unroll
        for (int j = 0; j < NI; j++)
#pragma unroll
            for (int q = 0; q < 4; q++) acc[i][j][q] = 0.f;

    auto load_tile = [&](int i, int st) {
        const int seg = i / tps;
        const long k0 = (long)(i - seg * tps) << 6;
        const bf16* Ap = ((seg == 2) ? Al : Ah);
        const bf16* Bp = ((seg == 1) ? Bl : Bh);
#pragma unroll
        for (int it = 0; it < 4; it++) {
            int f = tid + it * 256, r = f >> 3, c = f & 7;
            cp16(aS + st * ASTG + r * 128 + ((c ^ (r & 7)) << 4),
                 Ap + (m0 + r) * (long)lda + k0 + c * 8);
        }
#pragma unroll
        for (int it = 0; it < BN / 32; it++) {
            int f = tid + it * 256, r = f >> 3, c = f & 7;
            cp16(bS + st * BSTG + r * 128 + ((c ^ (r & 7)) << 4),
                 Bp + (n0 + r) * (long)ldb + k0 + c * 8);
        }
        cp_commit();
    };

    load_tile(0, 0);

    for (int i = 0; i < nt; i++) {
        const int st = i & 1;
        if (i + 1 < nt) { load_tile(i + 1, st ^ 1); cp_wait1(); }
        else            { cp_wait0(); }
        __syncthreads();

        const uint32_t aB = aS + st * ASTG;
        const uint32_t bB = bS + st * BSTG;
#pragma unroll
        for (int ks = 0; ks < 4; ks++) {
            uint32_t af[4][4];
#pragma unroll
            for (int mi = 0; mi < 4; mi++) {
                int r = wm * 64 + mi * 16 + (lane & 15);
                int c = ks * 2 + (lane >> 4);
                ldm_x4(af[mi][0], af[mi][1], af[mi][2], af[mi][3],
                       aB + r * 128 + ((c ^ (r & 7)) << 4));
            }
            uint32_t bfr[NI][2];
#pragma unroll
            for (int p = 0; p < NI / 2; p++) {
                int n = wn * (BN / 4) + p * 16 + (lane & 7) + ((lane >> 4) << 3);
                int c = ks * 2 + ((lane >> 3) & 1);
                uint32_t r0, r1, r2, r3;
                ldm_x4(r0, r1, r2, r3, bB + n * 128 + ((c ^ (n & 7)) << 4));
                bfr[2*p][0] = r0; bfr[2*p][1] = r1;
                bfr[2*p+1][0] = r2; bfr[2*p+1][1] = r3;
            }
#pragma unroll
            for (int mi = 0; mi < 4; mi++)
#pragma unroll
                for (int ni = 0; ni < NI; ni++)
                    mma16816(acc[mi][ni], af[mi], bfr[ni][0], bfr[ni][1]);
        }
        __syncthreads();
    }

    const long mw = m0 + wm * 64;
    const long nw = n0 + wn * (BN / 4);
#pragma unroll
    for (int mi = 0; mi < 4; mi++) {
#pragma unroll
        for (int ni = 0; ni < NI; ni++) {
            float* c = acc[mi][ni];
            long r0 = mw + mi * 16 + (lane >> 2);
            long cc = nw + ni * 8 + (lane & 3) * 2;
            float2 v0 = make_float2(c[0], c[1]);
            float2 v1 = make_float2(c[2], c[3]);
            if (bias) {
                float2 bv = *reinterpret_cast<const float2*>(bias + cc);
                v0.x += bv.x; v0.y += bv.y; v1.x += bv.x; v1.y += bv.y;
            }
            if (resid) {
                float2 ra = *reinterpret_cast<const float2*>(resid + r0 * ldc + cc);
                float2 rb = *reinterpret_cast<const float2*>(resid + (r0 + 8) * ldc + cc);
                v0.x += ra.x; v0.y += ra.y; v1.x += rb.x; v1.y += rb.y;
            }
            if (relu) {
                v0.x = fmaxf(v0.x, 0.f); v0.y = fmaxf(v0.y, 0.f);
                v1.x = fmaxf(v1.x, 0.f); v1.y = fmaxf(v1.y, 0.f);
            }
            if (CsH) {
                uint32_t h0, l0, h1, l1;
                pksplit(h0, l0, v0.x, v0.y);
                pksplit(h1, l1, v1.x, v1.y);
                *reinterpret_cast<uint32_t*>(CsH + r0 * ldc + cc) = h0;
                *reinterpret_cast<uint32_t*>(CsL + r0 * ldc + cc) = l0;
                *reinterpret_cast<uint32_t*>(CsH + (r0 + 8) * ldc + cc) = h1;
                *reinterpret_cast<uint32_t*>(CsL + (r0 + 8) * ldc + cc) = l1;
            } else {
                *reinterpret_cast<float2*>(C + r0 * ldc + cc) = v0;
                *reinterpret_cast<float2*>(C + (r0 + 8) * ldc + cc) = v1;
            }
        }
    }
}

// ---------------------------------------------------------------------------
// Fused flash attention: ctx = softmax(q k^T) v   (q pre-scaled by 1/8)
// One CTA = 128 q-rows of one head. 8 warps x 16 rows. Online softmax.
// smem: q hi/lo (32KB) + 2 stages of {kh,kl,vh,vl} (64KB each).
// ---------------------------------------------------------------------------
__global__ __launch_bounds__(256, 1)
void flash_attn(const bf16* __restrict__ qH, const bf16* __restrict__ qL,
                const bf16* __restrict__ kH, const bf16* __restrict__ kL,
                const bf16* __restrict__ vH, const bf16* __restrict__ vL,
                float* __restrict__ ctx)
{
    extern __shared__ char smem[];
    const uint32_t sb = smem_u32(smem);
    const int tid = threadIdx.x, wid = tid >> 5, lane = tid & 31;
    const int z = blockIdx.y;                       // b*16 + h
    const long qoff = ((long)z * SEQ + (long)blockIdx.x * 128) * HD;
    const long koff = (long)z * SEQ * HD;
    const long voff = (long)z * HD * SEQ;

    const uint32_t QHs = sb, QLs = sb + 16384, ST = sb + 32768;
    constexpr uint32_t STG = 65536;

    // q tiles (group 0)
#pragma unroll
    for (int it = 0; it < 4; it++) {
        int f = tid + it * 256, r = f >> 3, c = f & 7;
        cp16(QHs + r * 128 + ((c ^ (r & 7)) << 4), qH + qoff + r * 64 + c * 8);
    }
#pragma unroll
    for (int it = 0; it < 4; it++) {
        int f = tid + it * 256, r = f >> 3, c = f & 7;
        cp16(QLs + r * 128 + ((c ^ (r & 7)) << 4), qL + qoff + r * 64 + c * 8);
    }
    cp_commit();

    auto load_kv = [&](int t, int st) {
        const long t0 = (long)t * 128;
        const uint32_t B = ST + st * STG;
#pragma unroll
        for (int it = 0; it < 16; it++) {
            int f = tid + it * 256;
            int buf = f >> 10, g = f & 1023;
            if (buf == 0) {
                int r = g >> 3, c = g & 7;
                cp16(B + r * 128 + ((c ^ (r & 7)) << 4), kH + koff + (t0 + r) * 64 + c * 8);
            } else if (buf == 1) {
                int r = g >> 3, c = g & 7;
                cp16(B + 16384 + r * 128 + ((c ^ (r & 7)) << 4), kL + koff + (t0 + r) * 64 + c * 8);
            } else if (buf == 2) {
                int r = g >> 4, c = g & 15;
                cp16(B + 32768 + r * 256 + ((c ^ (r & 7)) << 4), vH + voff + (long)r * 1024 + t0 + c * 8);
            } else {
                int r = g >> 4, c = g & 15;
                cp16(B + 49152 + r * 256 + ((c ^ (r & 7)) << 4), vL + voff + (long)r * 1024 + t0 + c * 8);
            }
        }
        cp_commit();
    };

    load_kv(0, 0);
    cp_wait1();              // q done (only stage0 may be in flight)
    __syncthreads();

    uint32_t qh[4][4], ql[4][4];
#pragma unroll
    for (int ks = 0; ks < 4; ks++) {
        int r = wid * 16 + (lane & 15), c = ks * 2 + (lane >> 4);
        ldm_x4(qh[ks][0], qh[ks][1], qh[ks][2], qh[ks][3], QHs + r * 128 + ((c ^ (r & 7)) << 4));
        ldm_x4(ql[ks][0], ql[ks][1], ql[ks][2], ql[ks][3], QLs + r * 128 + ((c ^ (r & 7)) << 4));
    }

    float S[16][4], O[8][4];
    float m0 = -1e30f, m1 = -1e30f, l0 = 0.f, l1 = 0.f;
#pragma unroll
    for (int i = 0; i < 8; i++)
#pragma unroll
        for (int q = 0; q < 4; q++) O[i][q] = 0.f;

    for (int t = 0; t < 8; t++) {
        const int st = t & 1;
        if (t + 1 < 8) { load_kv(t + 1, st ^ 1); cp_wait1(); }
        else           { cp_wait0(); }
        __syncthreads();

#pragma unroll
        for (int i = 0; i < 16; i++)
#pragma unroll
            for (int q = 0; q < 4; q++) S[i][q] = 0.f;

        const uint32_t B = ST + st * STG;
        // S = qh kh^T + ql kh^T + qh kl^T
#pragma unroll
        for (int ks = 0; ks < 4; ks++) {
#pragma unroll
            for (int p = 0; p < 8; p++) {
                int n = p * 16 + (lane & 7) + ((lane >> 4) << 3);
                int c = ks * 2 + ((lane >> 3) & 1);
                uint32_t r0, r1, r2, r3;
                ldm_x4(r0, r1, r2, r3, B + n * 128 + ((c ^ (n & 7)) << 4));
                mma16816(S[2*p],   qh[ks], r0, r1);
                mma16816(S[2*p+1], qh[ks], r2, r3);
                mma16816(S[2*p],   ql[ks], r0, r1);
                mma16816(S[2*p+1], ql[ks], r2, r3);
                ldm_x4(r0, r1, r2, r3, B + 16384 + n * 128 + ((c ^ (n & 7)) << 4));
                mma16816(S[2*p],   qh[ks], r0, r1);
                mma16816(S[2*p+1], qh[ks], r2, r3);
            }
        }

        // online softmax
        float tm0 = -1e30f, tm1 = -1e30f;
#pragma unroll
        for (int i = 0; i < 16; i++) {
            tm0 = fmaxf(tm0, fmaxf(S[i][0], S[i][1]));
            tm1 = fmaxf(tm1, fmaxf(S[i][2], S[i][3]));
        }
#pragma unroll
        for (int o = 1; o <= 2; o <<= 1) {
            tm0 = fmaxf(tm0, __shfl_xor_sync(~0u, tm0, o));
            tm1 = fmaxf(tm1, __shfl_xor_sync(~0u, tm1, o));
        }
        float nm0 = fmaxf(m0, tm0), nm1 = fmaxf(m1, tm1);
        float sc0 = __expf(m0 - nm0), sc1 = __expf(m1 - nm1);
        m0 = nm0; m1 = nm1;
        float ls0 = 0.f, ls1 = 0.f;
#pragma unroll
        for (int i = 0; i < 16; i++) {
            S[i][0] = __expf(S[i][0] - m0); ls0 += S[i][0];
            S[i][1] = __expf(S[i][1] - m0); ls0 += S[i][1];
            S[i][2] = __expf(S[i][2] - m1); ls1 += S[i][2];
            S[i][3] = __expf(S[i][3] - m1); ls1 += S[i][3];
        }
#pragma unroll
        for (int o = 1; o <= 2; o <<= 1) {
            ls0 += __shfl_xor_sync(~0u, ls0, o);
            ls1 += __shfl_xor_sync(~0u, ls1, o);
        }
        l0 = l0 * sc0 + ls0;
        l1 = l1 * sc1 + ls1;
#pragma unroll
        for (int i = 0; i < 8; i++) {
            O[i][0] *= sc0; O[i][1] *= sc0;
            O[i][2] *= sc1; O[i][3] *= sc1;
        }

        // O += Ph Vh + Pl Vh + Ph Vl
#pragma unroll
        for (int j = 0; j < 8; j++) {
            uint32_t ph[4], pl[4];
            pksplit(ph[0], pl[0], S[2*j][0],   S[2*j][1]);
            pksplit(ph[1], pl[1], S[2*j][2],   S[2*j][3]);
            pksplit(ph[2], pl[2], S[2*j+1][0], S[2*j+1][1]);
            pksplit(ph[3], pl[3], S[2*j+1][2], S[2*j+1][3]);
#pragma unroll
            for (int p = 0; p < 4; p++) {
                int n = p * 16 + (lane & 7) + ((lane >> 4) << 3);
                int c = j * 2 + ((lane >> 3) & 1);
                uint32_t r0, r1, r2, r3;
                ldm_x4(r0, r1, r2, r3, B + 32768 + n * 256 + ((c ^ (n & 7)) << 4));
                mma16816(O[2*p],   ph, r0, r1);
                mma16816(O[2*p+1], ph, r2, r3);
                mma16816(O[2*p],   pl, r0, r1);
                mma16816(O[2*p+1], pl, r2, r3);
                ldm_x4(r0, r1, r2, r3, B + 49152 + n * 256 + ((c ^ (n & 7)) << 4));
                mma16816(O[2*p],   ph, r0, r1);
                mma16816(O[2*p+1], ph, r2, r3);
            }
        }
        __syncthreads();
    }

    // write ctx [s][b*1024 + h*64 + d], row stride 8192
    float inv0 = 1.f / l0, inv1 = 1.f / l1;
    long s0 = (long)blockIdx.x * 128 + wid * 16 + (lane >> 2);
    long cb = (long)(z >> 4) * 1024 + (long)(z & 15) * 64;
#pragma unroll
    for (int ni = 0; ni < 8; ni++) {
        long d0 = cb + ni * 8 + (lane & 3) * 2;
        float2 a = make_float2(O[ni][0] * inv0, O[ni][1] * inv0);
        float2 b = make_float2(O[ni][2] * inv1, O[ni][3] * inv1);
        *reinterpret_cast<float2*>(ctx + s0 * 8192 + d0) = a;
        *reinterpret_cast<float2*>(ctx + (s0 + 8) * 8192 + d0) = b;
    }
}

// ---------------- conversions ----------------------------------------------
__global__ void split2(const float* __restrict__ in, bf16* __restrict__ hi,
                       bf16* __restrict__ lo, long n4)
{
    long i = (long)blockIdx.x * blockDim.x + threadIdx.x;
    if (i >= n4) return;
    float4 v = reinterpret_cast<const float4*>(in)[i];
    bf16 h[4], l[4];
    split_hl(v.x, h[0], l[0]); split_hl(v.y, h[1], l[1]);
    split_hl(v.z, h[2], l[2]); split_hl(v.w, h[3], l[3]);
    reinterpret_cast<uint2*>(hi)[i] = *reinterpret_cast<uint2*>(h);
    reinterpret_cast<uint2*>(lo)[i] = *reinterpret_cast<uint2*>(l);
}

__global__ void qk_split(const float* __restrict__ qkv,
                         bf16* __restrict__ qH, bf16* __restrict__ qL,
                         bf16* __restrict__ kH, bf16* __restrict__ kL)
{
    long idx = (long)blockIdx.x * 256 + threadIdx.x;
    int row = (int)(idx >> 10), c = (int)(idx & 1023);
    int s = row >> 3, b = row & 7, h = c >> 6, d = c & 63;
    float qv = qkv[(long)row * 3072 + c] * 0.125f;
    float kv = qkv[(long)row * 3072 + 1024 + c];
    long o = (((long)(b * 16 + h)) * 1024 + s) * 64 + d;
    bf16 hh, ll;
    split_hl(qv, hh, ll); qH[o] = hh; qL[o] = ll;
    split_hl(kv, hh, ll); kH[o] = hh; kL[o] = ll;
}

__global__ void v_split(const float* __restrict__ qkv,
                        bf16* __restrict__ vtH, bf16* __restrict__ vtL)
{
    int bx = blockIdx.x;
    int z = bx >> 7, tb = bx & 127;
    int b = z >> 4, h = z & 15, d = threadIdx.x;
    bf16 hs[8], ls[8];
#pragma unroll
    for (int tt = 0; tt < 8; tt++) {
        int t = tb * 8 + tt;
        float v = qkv[((long)(t * 8 + b)) * 3072 + 2048 + h * 64 + d];
        split_hl(v, hs[tt], ls[tt]);
    }
    long o = ((long)(z * 64 + d)) * 1024 + tb * 8;
    *reinterpret_cast<uint4*>(vtH + o) = *reinterpret_cast<uint4*>(hs);
    *reinterpret_cast<uint4*>(vtL + o) = *reinterpret_cast<uint4*>(ls);
}

__global__ void layernorm_kernel(const float* __restrict__ in, const float* __restrict__ g,
                                 const float* __restrict__ b, float* __restrict__ out)
{
    __shared__ float rs[8], rq[8];
    const long row = blockIdx.x;
    const int tid = threadIdx.x;
    float4 x = reinterpret_cast<const float4*>(in + row * (long)DM)[tid];
    float s = x.x + x.y + x.z + x.w;
    float q = x.x*x.x + x.y*x.y + x.z*x.z + x.w*x.w;
#pragma unroll
    for (int o = 16; o > 0; o >>= 1) {
        s += __shfl_xor_sync(~0u, s, o);
        q += __shfl_xor_sync(~0u, q, o);
    }
    if ((tid & 31) == 0) { rs[tid >> 5] = s; rq[tid >> 5] = q; }
    __syncthreads();
    float ts = 0.f, tq = 0.f;
#pragma unroll
    for (int i = 0; i < 8; i++) { ts += rs[i]; tq += rq[i]; }
    const float mu = ts * (1.f / DM);
    const float var = tq * (1.f / DM) - mu * mu;
    const float r = rsqrtf(var + EPS);
    float4 gg = reinterpret_cast<const float4*>(g)[tid];
    float4 bb = reinterpret_cast<const float4*>(b)[tid];
    float4 y;
    y.x = (x.x - mu) * r * gg.x + bb.x;
    y.y = (x.y - mu) * r * gg.y + bb.y;
    y.z = (x.z - mu) * r * gg.z + bb.z;
    y.w = (x.w - mu) * r * gg.w + bb.w;
    reinterpret_cast<float4*>(out + row * (long)DM)[tid] = y;
}

// ---------------- host ------------------------------------------------------
#define SYMADDR(p, s) do { void* v_; cudaGetSymbolAddress(&v_, s); p = (decltype(p))v_; } while (0)

extern "C" void kernel_launch(void* const* d_in, const int* in_sizes, int n_in,
                              void* d_out, int out_size)
{
    (void)in_sizes; (void)n_in; (void)out_size;
    const float* src = (const float*)d_in[0];
    const float* in_proj_w = (const float*)d_in[1];
    const float* in_proj_b = (const float*)d_in[2];
    const float* out_w = (const float*)d_in[3];
    const float* out_b = (const float*)d_in[4];
    const float* w1 = (const float*)d_in[5];
    const float* b1 = (const float*)d_in[6];
    const float* w2 = (const float*)d_in[7];
    const float* b2 = (const float*)d_in[8];
    const float* g1 = (const float*)d_in[9];
    const float* be1 = (const float*)d_in[10];
    const float* g2 = (const float*)d_in[11];
    const float* be2 = (const float*)d_in[12];
    float* out = (float*)d_out;

    float *p_qkv, *p_ctx, *p_x, *p_tmp;
    bf16 *srcH, *srcL, *wiH, *wiL, *owH, *owL, *w1H, *w1L, *w2H, *w2L;
    bf16 *qH, *qL, *kH, *kL, *vtH, *vtL, *ctxH, *ctxL, *xH, *xL, *h1H, *h1L;
    SYMADDR(p_qkv, g_qkv); SYMADDR(p_ctx, g_ctx);
    SYMADDR(p_x, g_x); SYMADDR(p_tmp, g_tmp);
    SYMADDR(srcH, g_srcH); SYMADDR(srcL, g_srcL);
    SYMADDR(wiH, g_wiH); SYMADDR(wiL, g_wiL);
    SYMADDR(owH, g_owH); SYMADDR(owL, g_owL);
    SYMADDR(w1H, g_w1H); SYMADDR(w1L, g_w1L);
    SYMADDR(w2H, g_w2H); SYMADDR(w2L, g_w2L);
    SYMADDR(qH, g_qH); SYMADDR(qL, g_qL); SYMADDR(kH, g_kH); SYMADDR(kL, g_kL);
    SYMADDR(vtH, g_vtH); SYMADDR(vtL, g_vtL);
    SYMADDR(ctxH, g_ctxH); SYMADDR(ctxL, g_ctxL);
    SYMADDR(xH, g_xH); SYMADDR(xL, g_xL);
    SYMADDR(h1H, g_h1H); SYMADDR(h1L, g_h1L);

    const int SM128 = 4 * (128 * 128);   // 64 KB
    const int FASM  = 32768 + 2 * 65536; // 160 KB
    cudaFuncSetAttribute(gemm_mma<128>, cudaFuncAttributeMaxDynamicSharedMemorySize, SM128);
    cudaFuncSetAttribute(flash_attn, cudaFuncAttributeMaxDynamicSharedMemorySize, FASM);

    auto spl = [](const float* in, bf16* h, bf16* l, long n) {
        long n4 = n >> 2;
        split2<<<(unsigned)((n4 + 255) / 256), 256>>>(in, h, l, n4);
    };

    // splits
    spl(src, srcH, srcL, (long)SB * DM);
    spl(in_proj_w, wiH, wiL, (long)3 * DM * DM);
    spl(out_w, owH, owL, (long)DM * DM);
    spl(w1, w1H, w1L, (long)FF * DM);
    spl(w2, w2H, w2L, (long)DM * FF);

    // 1) QKV = src @ in_proj_w^T + b
    gemm_mma<128><<<dim3(24, 64, 1), 256, SM128>>>(
        srcH, srcL, DM, 0, wiH, wiL, DM, 0,
        in_proj_b, nullptr, p_qkv, nullptr, nullptr, 3 * DM, 0, 0, 1, DM, 0);

    // 2) head-major splits
    qk_split<<<SB * DM / 256, 256>>>(p_qkv, qH, qL, kH, kL);
    v_split<<<BATCH * NH * 128, 64>>>(p_qkv, vtH, vtL);

    // 3) fused attention -> ctx fp32
    flash_attn<<<dim3(8, BATCH * NH), 256, FASM>>>(qH, qL, kH, kL, vtH, vtL, p_ctx);

    // 4) tmp = ctx @ out_w^T + out_b + src ; x = LN1
    spl(p_ctx, ctxH, ctxL, (long)SB * DM);
    gemm_mma<128><<<dim3(8, 64, 1), 256, SM128>>>(
        ctxH, ctxL, DM, 0, owH, owL, DM, 0,
        out_b, src, p_tmp, nullptr, nullptr, DM, 0, 0, 1, DM, 0);
    layernorm_kernel<<<SB, 256>>>(p_tmp, g1, be1, p_x);

    // 5) FFN1: h1 = relu(x @ w1^T + b1) -> bf16 hi/lo directly
    spl(p_x, xH, xL, (long)SB * DM);
    gemm_mma<128><<<dim3(32, 64, 1), 256, SM128>>>(
        xH, xL, DM, 0, w1H, w1L, DM, 0,
        b1, nullptr, nullptr, h1H, h1L, FF, 0, 0, 1, DM, 1);

    // 6) FFN2: tmp = h1 @ w2^T + b2 + x
    gemm_mma<128><<<dim3(8, 64, 1), 256, SM128>>>(
        h1H, h1L, FF, 0, w2H, w2L, FF, 0,
        b2, p_x, p_tmp, nullptr, nullptr, DM, 0, 0, 1, FF, 0);

    // 7) out = LN2
    layernorm_kernel<<<SB, 256>>>(p_tmp, g2, be2, out);
}

// round 6
// speedup vs baseline: 2.7425x; 2.7425x over previous
#include <cuda_runtime.h>
#include <cuda_fp16.h>
#include <cstdint>

typedef __half fp16;
constexpr int SEQ = 1024, BATCH = 8, DM = 1024, NH = 16, HD = 64, FF = 4096;
constexpr int SB = SEQ * BATCH;
constexpr float EPS = 1e-5f;

// ---------------- scratch (device globals; no allocation allowed) ----------
__device__ float g_qkv[(size_t)SB * 3 * DM];   // 96 MB
__device__ float g_x[(size_t)SB * DM];         // 32 MB
__device__ float g_tmp[(size_t)SB * DM];       // 32 MB

__device__ fp16 g_srcH[(size_t)SB * DM];
__device__ fp16 g_wiH[(size_t)3 * DM * DM];
__device__ fp16 g_owH[(size_t)DM * DM];
__device__ fp16 g_w1H[(size_t)FF * DM];
__device__ fp16 g_w2H[(size_t)DM * FF];
__device__ fp16 g_qH[(size_t)BATCH * NH * SEQ * HD];
__device__ fp16 g_kH[(size_t)BATCH * NH * SEQ * HD];
__device__ fp16 g_vtH[(size_t)BATCH * NH * HD * SEQ];
__device__ fp16 g_ctxH[(size_t)SB * DM];
__device__ fp16 g_xH[(size_t)SB * DM];
__device__ fp16 g_h1H[(size_t)SB * FF];

// ---------------- helpers ---------------------------------------------------
__device__ __forceinline__ uint32_t smem_u32(const void* p) {
    uint32_t a;
    asm("{ .reg .u64 t; cvta.to.shared.u64 t, %1; cvt.u32.u64 %0, t; }" : "=r"(a) : "l"(p));
    return a;
}
__device__ __forceinline__ void cp16(uint32_t saddr, const void* gaddr) {
    asm volatile("cp.async.cg.shared.global [%0], [%1], 16;" :: "r"(saddr), "l"(gaddr));
}
__device__ __forceinline__ void cp_commit() { asm volatile("cp.async.commit_group;"); }
__device__ __forceinline__ void cp_wait1()  { asm volatile("cp.async.wait_group 1;"); }
__device__ __forceinline__ void cp_wait0()  { asm volatile("cp.async.wait_group 0;"); }
__device__ __forceinline__ void ldm_x4(uint32_t& r0, uint32_t& r1, uint32_t& r2, uint32_t& r3,
                                       uint32_t addr) {
    asm volatile("ldmatrix.sync.aligned.m8n8.x4.shared.b16 {%0,%1,%2,%3}, [%4];"
                 : "=r"(r0), "=r"(r1), "=r"(r2), "=r"(r3) : "r"(addr));
}
__device__ __forceinline__ void mma16816(float* c, const uint32_t* a, uint32_t b0, uint32_t b1) {
    asm volatile("mma.sync.aligned.m16n8k16.row.col.f32.f16.f16.f32 "
                 "{%0,%1,%2,%3}, {%4,%5,%6,%7}, {%8,%9}, {%0,%1,%2,%3};"
                 : "+f"(c[0]), "+f"(c[1]), "+f"(c[2]), "+f"(c[3])
                 : "r"(a[0]), "r"(a[1]), "r"(a[2]), "r"(a[3]), "r"(b0), "r"(b1));
}
__device__ __forceinline__ uint32_t pk2h(float a, float b) {
    __half2 t = __floats2half2_rn(a, b);
    return *reinterpret_cast<uint32_t*>(&t);
}

// ---------------------------------------------------------------------------
// fp16 HMMA GEMM, single pass.
//   C[m,n] = sum_k A[m,k] * B[n,k]    (both row-major, K contiguous)
// BM = 128, BN = 128, BK = 64. 256 threads, warp grid 2(m) x 4(n).
// Epilogue: fp32 C (+bias +resid +relu) or fp16 Ch (+bias +relu).
// ---------------------------------------------------------------------------
__global__ __launch_bounds__(256, 1)
void gemm16(const fp16* __restrict__ A, int lda,
            const fp16* __restrict__ B, int ldb,
            const float* __restrict__ bias, const float* __restrict__ resid,
            float* __restrict__ C, fp16* __restrict__ Ch,
            int ldc, int K, int relu)
{
    extern __shared__ char smem[];
    const uint32_t sbase = smem_u32(smem);
    constexpr int ASTG = 128 * 128;     // 16 KB per stage
    const uint32_t aS = sbase;
    const uint32_t bS = sbase + 2 * ASTG;

    const int tid = threadIdx.x, wid = tid >> 5, lane = tid & 31;
    const int wm = wid >> 2, wn = wid & 3;

    const long m0 = (long)blockIdx.y * 128;
    const long n0 = (long)blockIdx.x * 128;
    const int nt = K >> 6;

    float acc[4][4][4];
#pragma unroll
    for (int i = 0; i < 4; i++)
#pragma unroll
        for (int j = 0; j < 4; j++)
#pragma unroll
            for (int q = 0; q < 4; q++) acc[i][j][q] = 0.f;

    auto load_tile = [&](int i, int st) {
        const long k0 = (long)i << 6;
#pragma unroll
        for (int it = 0; it < 4; it++) {
            int f = tid + it * 256, r = f >> 3, c = f & 7;
            cp16(aS + st * ASTG + r * 128 + ((c ^ (r & 7)) << 4),
                 A + (m0 + r) * (long)lda + k0 + c * 8);
        }
#pragma unroll
        for (int it = 0; it < 4; it++) {
            int f = tid + it * 256, r = f >> 3, c = f & 7;
            cp16(bS + st * ASTG + r * 128 + ((c ^ (r & 7)) << 4),
                 B + (n0 + r) * (long)ldb + k0 + c * 8);
        }
        cp_commit();
    };

    load_tile(0, 0);

    for (int i = 0; i < nt; i++) {
        const int st = i & 1;
        if (i + 1 < nt) { load_tile(i + 1, st ^ 1); cp_wait1(); }
        else            { cp_wait0(); }
        __syncthreads();

        const uint32_t aB = aS + st * ASTG;
        const uint32_t bB = bS + st * ASTG;
#pragma unroll
        for (int ks = 0; ks < 4; ks++) {
            uint32_t af[4][4];
#pragma unroll
            for (int mi = 0; mi < 4; mi++) {
                int r = wm * 64 + mi * 16 + (lane & 15);
                int c = ks * 2 + (lane >> 4);
                ldm_x4(af[mi][0], af[mi][1], af[mi][2], af[mi][3],
                       aB + r * 128 + ((c ^ (r & 7)) << 4));
            }
            uint32_t bfr[4][2];
#pragma unroll
            for (int p = 0; p < 2; p++) {
                int n = wn * 32 + p * 16 + (lane & 7) + ((lane >> 4) << 3);
                int c = ks * 2 + ((lane >> 3) & 1);
                uint32_t r0, r1, r2, r3;
                ldm_x4(r0, r1, r2, r3, bB + n * 128 + ((c ^ (n & 7)) << 4));
                bfr[2*p][0] = r0; bfr[2*p][1] = r1;
                bfr[2*p+1][0] = r2; bfr[2*p+1][1] = r3;
            }
#pragma unroll
            for (int mi = 0; mi < 4; mi++)
#pragma unroll
                for (int ni = 0; ni < 4; ni++)
                    mma16816(acc[mi][ni], af[mi], bfr[ni][0], bfr[ni][1]);
        }
        __syncthreads();
    }

    const long mw = m0 + wm * 64;
    const long nw = n0 + wn * 32;
#pragma unroll
    for (int mi = 0; mi < 4; mi++) {
#pragma unroll
        for (int ni = 0; ni < 4; ni++) {
            float* c = acc[mi][ni];
            long r0 = mw + mi * 16 + (lane >> 2);
            long cc = nw + ni * 8 + (lane & 3) * 2;
            float2 v0 = make_float2(c[0], c[1]);
            float2 v1 = make_float2(c[2], c[3]);
            if (bias) {
                float2 bv = *reinterpret_cast<const float2*>(bias + cc);
                v0.x += bv.x; v0.y += bv.y; v1.x += bv.x; v1.y += bv.y;
            }
            if (resid) {
                float2 ra = *reinterpret_cast<const float2*>(resid + r0 * ldc + cc);
                float2 rb = *reinterpret_cast<const float2*>(resid + (r0 + 8) * ldc + cc);
                v0.x += ra.x; v0.y += ra.y; v1.x += rb.x; v1.y += rb.y;
            }
            if (relu) {
                v0.x = fmaxf(v0.x, 0.f); v0.y = fmaxf(v0.y, 0.f);
                v1.x = fmaxf(v1.x, 0.f); v1.y = fmaxf(v1.y, 0.f);
            }
            if (Ch) {
                *reinterpret_cast<uint32_t*>(Ch + r0 * ldc + cc) = pk2h(v0.x, v0.y);
                *reinterpret_cast<uint32_t*>(Ch + (r0 + 8) * ldc + cc) = pk2h(v1.x, v1.y);
            } else {
                *reinterpret_cast<float2*>(C + r0 * ldc + cc) = v0;
                *reinterpret_cast<float2*>(C + (r0 + 8) * ldc + cc) = v1;
            }
        }
    }
}

// ---------------------------------------------------------------------------
// Fused flash attention (fp16 single): ctx = softmax(q k^T) v, q pre-scaled.
// CTA = 128 q-rows of one head; 8 warps x 16 rows; online softmax.
// smem: q (16KB) + 2 stages of {k 16KB, vt 16KB} = 80 KB.
// ---------------------------------------------------------------------------
__global__ __launch_bounds__(256, 1)
void flash16(const fp16* __restrict__ qH, const fp16* __restrict__ kH,
             const fp16* __restrict__ vH, fp16* __restrict__ ctx)
{
    extern __shared__ char smem[];
    const uint32_t sb = smem_u32(smem);
    const int tid = threadIdx.x, wid = tid >> 5, lane = tid & 31;
    const int z = blockIdx.y;                        // b*16 + h
    const long qoff = ((long)z * SEQ + (long)blockIdx.x * 128) * HD;
    const long koff = (long)z * SEQ * HD;
    const long voff = (long)z * HD * SEQ;

    const uint32_t Qs = sb, ST = sb + 16384;
    constexpr uint32_t STG = 32768;

    // q (one cp.async group)
#pragma unroll
    for (int it = 0; it < 4; it++) {
        int f = tid + it * 256, r = f >> 3, c = f & 7;
        cp16(Qs + r * 128 + ((c ^ (r & 7)) << 4), qH + qoff + r * 64 + c * 8);
    }
    cp_commit();

    auto load_kv = [&](int t, int st) {
        const long t0 = (long)t * 128;
        const uint32_t B = ST + st * STG;
#pragma unroll
        for (int it = 0; it < 4; it++) {             // k tile 128x64
            int f = tid + it * 256, r = f >> 3, c = f & 7;
            cp16(B + r * 128 + ((c ^ (r & 7)) << 4), kH + koff + (t0 + r) * 64 + c * 8);
        }
#pragma unroll
        for (int it = 0; it < 4; it++) {             // v tile 64x128 (t-major)
            int f = tid + it * 256, r = f >> 4, c = f & 15;
            cp16(B + 16384 + r * 256 + ((c ^ (r & 7)) << 4),
                 vH + voff + (long)r * 1024 + t0 + c * 8);
        }
        cp_commit();
    };

    load_kv(0, 0);
    cp_wait1();                 // q group complete
    __syncthreads();

    uint32_t qf[4][4];
#pragma unroll
    for (int ks = 0; ks < 4; ks++) {
        int r = wid * 16 + (lane & 15), c = ks * 2 + (lane >> 4);
        ldm_x4(qf[ks][0], qf[ks][1], qf[ks][2], qf[ks][3],
               Qs + r * 128 + ((c ^ (r & 7)) << 4));
    }

    float S[16][4], O[8][4];
    float m0 = -1e30f, m1 = -1e30f, l0 = 0.f, l1 = 0.f;
#pragma unroll
    for (int i = 0; i < 8; i++)
#pragma unroll
        for (int q = 0; q < 4; q++) O[i][q] = 0.f;

    for (int t = 0; t < 8; t++) {
        const int st = t & 1;
        if (t + 1 < 8) { load_kv(t + 1, st ^ 1); cp_wait1(); }
        else           { cp_wait0(); }
        __syncthreads();

#pragma unroll
        for (int i = 0; i < 16; i++)
#pragma unroll
            for (int q = 0; q < 4; q++) S[i][q] = 0.f;

        const uint32_t B = ST + st * STG;
#pragma unroll
        for (int ks = 0; ks < 4; ks++) {
#pragma unroll
            for (int p = 0; p < 8; p++) {
                int n = p * 16 + (lane & 7) + ((lane >> 4) << 3);
                int c = ks * 2 + ((lane >> 3) & 1);
                uint32_t r0, r1, r2, r3;
                ldm_x4(r0, r1, r2, r3, B + n * 128 + ((c ^ (n & 7)) << 4));
                mma16816(S[2*p],   qf[ks], r0, r1);
                mma16816(S[2*p+1], qf[ks], r2, r3);
            }
        }

        // online softmax (each thread covers 2 row groups: c0/c1 and c2/c3)
        float tm0 = -1e30f, tm1 = -1e30f;
#pragma unroll
        for (int i = 0; i < 16; i++) {
            tm0 = fmaxf(tm0, fmaxf(S[i][0], S[i][1]));
            tm1 = fmaxf(tm1, fmaxf(S[i][2], S[i][3]));
        }
#pragma unroll
        for (int o = 1; o <= 2; o <<= 1) {
            tm0 = fmaxf(tm0, __shfl_xor_sync(~0u, tm0, o));
            tm1 = fmaxf(tm1, __shfl_xor_sync(~0u, tm1, o));
        }
        float nm0 = fmaxf(m0, tm0), nm1 = fmaxf(m1, tm1);
        float sc0 = __expf(m0 - nm0), sc1 = __expf(m1 - nm1);
        m0 = nm0; m1 = nm1;
        float ls0 = 0.f, ls1 = 0.f;
#pragma unroll
        for (int i = 0; i < 16; i++) {
            S[i][0] = __expf(S[i][0] - m0); ls0 += S[i][0];
            S[i][1] = __expf(S[i][1] - m0); ls0 += S[i][1];
            S[i][2] = __expf(S[i][2] - m1); ls1 += S[i][2];
            S[i][3] = __expf(S[i][3] - m1); ls1 += S[i][3];
        }
#pragma unroll
        for (int o = 1; o <= 2; o <<= 1) {
            ls0 += __shfl_xor_sync(~0u, ls0, o);
            ls1 += __shfl_xor_sync(~0u, ls1, o);
        }
        l0 = l0 * sc0 + ls0;
        l1 = l1 * sc1 + ls1;
#pragma unroll
        for (int i = 0; i < 8; i++) {
            O[i][0] *= sc0; O[i][1] *= sc0;
            O[i][2] *= sc1; O[i][3] *= sc1;
        }

        // O += P V
#pragma unroll
        for (int j = 0; j < 8; j++) {
            uint32_t ph[4];
            ph[0] = pk2h(S[2*j][0],   S[2*j][1]);
            ph[1] = pk2h(S[2*j][2],   S[2*j][3]);
            ph[2] = pk2h(S[2*j+1][0], S[2*j+1][1]);
            ph[3] = pk2h(S[2*j+1][2], S[2*j+1][3]);
#pragma unroll
            for (int p = 0; p < 4; p++) {
                int n = p * 16 + (lane & 7) + ((lane >> 4) << 3);
                int c = j * 2 + ((lane >> 3) & 1);
                uint32_t r0, r1, r2, r3;
                ldm_x4(r0, r1, r2, r3, B + 16384 + n * 256 + ((c ^ (n & 7)) << 4));
                mma16816(O[2*p],   ph, r0, r1);
                mma16816(O[2*p+1], ph, r2, r3);
            }
        }
        __syncthreads();
    }

    // write ctx fp16 at [s][b*1024 + h*64 + d], row stride 8192
    float inv0 = 1.f / l0, inv1 = 1.f / l1;
    long s0 = (long)blockIdx.x * 128 + wid * 16 + (lane >> 2);
    long cb = (long)(z >> 4) * 1024 + (long)(z & 15) * 64;
#pragma unroll
    for (int ni = 0; ni < 8; ni++) {
        long d0 = cb + ni * 8 + (lane & 3) * 2;
        *reinterpret_cast<uint32_t*>(ctx + s0 * 8192 + d0) =
            pk2h(O[ni][0] * inv0, O[ni][1] * inv0);
        *reinterpret_cast<uint32_t*>(ctx + (s0 + 8) * 8192 + d0) =
            pk2h(O[ni][2] * inv1, O[ni][3] * inv1);
    }
}

// ---------------- conversions ----------------------------------------------
__global__ void cvt_h(const float* __restrict__ in, fp16* __restrict__ out, long n4)
{
    long i = (long)blockIdx.x * blockDim.x + threadIdx.x;
    if (i >= n4) return;
    float4 v = reinterpret_cast<const float4*>(in)[i];
    uint2 o;
    o.x = pk2h(v.x, v.y);
    o.y = pk2h(v.z, v.w);
    reinterpret_cast<uint2*>(out)[i] = o;
}

// qkv fp32 [row=s*8+b, 3072] -> q (x0.125), k fp16 head-major [z, s, 64]
__global__ void qk_split(const float* __restrict__ qkv,
                         fp16* __restrict__ qH, fp16* __restrict__ kH)
{
    long idx = (long)blockIdx.x * 256 + threadIdx.x;     // 4M pairs
    int row = (int)(idx >> 9), c2 = (int)(idx & 511);
    int c = c2 * 2;
    int s = row >> 3, b = row & 7, h = c >> 6, d = c & 63;
    const float* p = qkv + (long)row * 3072;
    float2 qv = *reinterpret_cast<const float2*>(p + c);
    float2 kv = *reinterpret_cast<const float2*>(p + 1024 + c);
    long o = (((long)(b * 16 + h)) * 1024 + s) * 64 + d;
    *reinterpret_cast<uint32_t*>(qH + o) = pk2h(qv.x * 0.125f, qv.y * 0.125f);
    *reinterpret_cast<uint32_t*>(kH + o) = pk2h(kv.x, kv.y);
}

// v from qkv -> vt fp16 [z, d, t]
__global__ void v_split(const float* __restrict__ qkv, fp16* __restrict__ vtH)
{
    int bx = blockIdx.x;
    int z = bx >> 7, tb = bx & 127;
    int b = z >> 4, h = z & 15, d = threadIdx.x;
    fp16 hs[8];
#pragma unroll
    for (int tt = 0; tt < 8; tt++) {
        int t = tb * 8 + tt;
        hs[tt] = __float2half_rn(qkv[((long)(t * 8 + b)) * 3072 + 2048 + h * 64 + d]);
    }
    long o = ((long)(z * 64 + d)) * 1024 + tb * 8;
    *reinterpret_cast<uint4*>(vtH + o) = *reinterpret_cast<uint4*>(hs);
}

// LayerNorm; optionally also emit fp16 copy of the output.
__global__ void layernorm_kernel(const float* __restrict__ in, const float* __restrict__ g,
                                 const float* __restrict__ b, float* __restrict__ out,
                                 fp16* __restrict__ out_h)
{
    __shared__ float rs[8], rq[8];
    const long row = blockIdx.x;
    const int tid = threadIdx.x;
    float4 x = reinterpret_cast<const float4*>(in + row * (long)DM)[tid];
    float s = x.x + x.y + x.z + x.w;
    float q = x.x*x.x + x.y*x.y + x.z*x.z + x.w*x.w;
#pragma unroll
    for (int o = 16; o > 0; o >>= 1) {
        s += __shfl_xor_sync(~0u, s, o);
        q += __shfl_xor_sync(~0u, q, o);
    }
    if ((tid & 31) == 0) { rs[tid >> 5] = s; rq[tid >> 5] = q; }
    __syncthreads();
    float ts = 0.f, tq = 0.f;
#pragma unroll
    for (int i = 0; i < 8; i++) { ts += rs[i]; tq += rq[i]; }
    const float mu = ts * (1.f / DM);
    const float var = tq * (1.f / DM) - mu * mu;
    const float r = rsqrtf(var + EPS);
    float4 gg = reinterpret_cast<const float4*>(g)[tid];
    float4 bb = reinterpret_cast<const float4*>(b)[tid];
    float4 y;
    y.x = (x.x - mu) * r * gg.x + bb.x;
    y.y = (x.y - mu) * r * gg.y + bb.y;
    y.z = (x.z - mu) * r * gg.z + bb.z;
    y.w = (x.w - mu) * r * gg.w + bb.w;
    if (out)
        reinterpret_cast<float4*>(out + row * (long)DM)[tid] = y;
    if (out_h) {
        uint2 o;
        o.x = pk2h(y.x, y.y);
        o.y = pk2h(y.z, y.w);
        reinterpret_cast<uint2*>(out_h + row * (long)DM)[tid] = o;
    }
}

// ---------------- host ------------------------------------------------------
#define SYMADDR(p, s) do { void* v_; cudaGetSymbolAddress(&v_, s); p = (decltype(p))v_; } while (0)

extern "C" void kernel_launch(void* const* d_in, const int* in_sizes, int n_in,
                              void* d_out, int out_size)
{
    (void)in_sizes; (void)n_in; (void)out_size;
    const float* src = (const float*)d_in[0];
    const float* in_proj_w = (const float*)d_in[1];
    const float* in_proj_b = (const float*)d_in[2];
    const float* out_w = (const float*)d_in[3];
    const float* out_b = (const float*)d_in[4];
    const float* w1 = (const float*)d_in[5];
    const float* b1 = (const float*)d_in[6];
    const float* w2 = (const float*)d_in[7];
    const float* b2 = (const float*)d_in[8];
    const float* g1 = (const float*)d_in[9];
    const float* be1 = (const float*)d_in[10];
    const float* g2 = (const float*)d_in[11];
    const float* be2 = (const float*)d_in[12];
    float* out = (float*)d_out;

    float *p_qkv, *p_x, *p_tmp;
    fp16 *srcH, *wiH, *owH, *w1H, *w2H, *qH, *kH, *vtH, *ctxH, *xH, *h1H;
    SYMADDR(p_qkv, g_qkv); SYMADDR(p_x, g_x); SYMADDR(p_tmp, g_tmp);
    SYMADDR(srcH, g_srcH); SYMADDR(wiH, g_wiH); SYMADDR(owH, g_owH);
    SYMADDR(w1H, g_w1H); SYMADDR(w2H, g_w2H);
    SYMADDR(qH, g_qH); SYMADDR(kH, g_kH); SYMADDR(vtH, g_vtH);
    SYMADDR(ctxH, g_ctxH); SYMADDR(xH, g_xH); SYMADDR(h1H, g_h1H);

    const int GSM  = 4 * (128 * 128) / 2 * 2;     // 64 KB (2 stages x (A16K + B16K))
    const int FASM = 16384 + 2 * 32768;           // 80 KB
    cudaFuncSetAttribute(gemm16, cudaFuncAttributeMaxDynamicSharedMemorySize, GSM);
    cudaFuncSetAttribute(flash16, cudaFuncAttributeMaxDynamicSharedMemorySize, FASM);

    auto cvt = [](const float* in, fp16* o, long n) {
        long n4 = n >> 2;
        cvt_h<<<(unsigned)((n4 + 255) / 256), 256>>>(in, o, n4);
    };

    // fp16 conversions of inputs
    cvt(src, srcH, (long)SB * DM);
    cvt(in_proj_w, wiH, (long)3 * DM * DM);
    cvt(out_w, owH, (long)DM * DM);
    cvt(w1, w1H, (long)FF * DM);
    cvt(w2, w2H, (long)DM * FF);

    // 1) QKV = src @ in_proj_w^T + b  -> fp32 qkv
    gemm16<<<dim3(24, 64), 256, GSM>>>(srcH, DM, wiH, DM,
                                       in_proj_b, nullptr, p_qkv, nullptr, 3 * DM, DM, 0);

    // 2) head-major fp16 splits
    qk_split<<<SB * DM / 512, 256>>>(p_qkv, qH, kH);
    v_split<<<BATCH * NH * 128, 64>>>(p_qkv, vtH);

    // 3) fused attention -> ctx fp16
    flash16<<<dim3(8, BATCH * NH), 256, FASM>>>(qH, kH, vtH, ctxH);

    // 4) tmp = ctx @ out_w^T + out_b + src ; x = LN1 (fp32 + fp16)
    gemm16<<<dim3(8, 64), 256, GSM>>>(ctxH, DM, owH, DM,
                                      out_b, src, p_tmp, nullptr, DM, DM, 0);
    layernorm_kernel<<<SB, 256>>>(p_tmp, g1, be1, p_x, xH);

    // 5) FFN1: h1 = relu(x @ w1^T + b1) -> fp16 directly
    gemm16<<<dim3(32, 64), 256, GSM>>>(xH, DM, w1H, DM,
                                       b1, nullptr, nullptr, h1H, FF, DM, 1);

    // 6) FFN2: tmp = h1 @ w2^T + b2 + x
    gemm16<<<dim3(8, 64), 256, GSM>>>(h1H, FF, w2H, FF,
                                      b2, p_x, p_tmp, nullptr, DM, FF, 0);

    // 7) out = LN2
    layernorm_kernel<<<SB, 256>>>(p_tmp, g2, be2, out, nullptr);
}

// round 7
// speedup vs baseline: 4.6886x; 1.7096x over previous
#include <cuda_runtime.h>
#include <cuda_fp16.h>
#include <cstdint>

typedef __half fp16;
constexpr int SEQ = 1024, BATCH = 8, DM = 1024, NH = 16, HD = 64, FF = 4096;
constexpr int SB = SEQ * BATCH;
constexpr float EPS = 1e-5f;

// ---------------- scratch (device globals; no allocation allowed) ----------
__device__ float g_x[(size_t)SB * DM];         // 32 MB
__device__ float g_tmp[(size_t)SB * DM];       // 32 MB

__device__ fp16 g_srcH[(size_t)SB * DM];
__device__ fp16 g_wiH[(size_t)3 * DM * DM];
__device__ fp16 g_owH[(size_t)DM * DM];
__device__ fp16 g_w1H[(size_t)FF * DM];
__device__ fp16 g_w2H[(size_t)DM * FF];
__device__ fp16 g_qH[(size_t)BATCH * NH * SEQ * HD];
__device__ fp16 g_kH[(size_t)BATCH * NH * SEQ * HD];
__device__ fp16 g_vsd[(size_t)BATCH * NH * SEQ * HD];   // v [z, s, d]
__device__ fp16 g_vtH[(size_t)BATCH * NH * HD * SEQ];   // v [z, d, t]
__device__ fp16 g_ctxH[(size_t)SB * DM];
__device__ fp16 g_xH[(size_t)SB * DM];
__device__ fp16 g_h1H[(size_t)SB * FF];

// ---------------- helpers ---------------------------------------------------
__device__ __forceinline__ uint32_t smem_u32(const void* p) {
    uint32_t a;
    asm("{ .reg .u64 t; cvta.to.shared.u64 t, %1; cvt.u32.u64 %0, t; }" : "=r"(a) : "l"(p));
    return a;
}
__device__ __forceinline__ void cp16(uint32_t saddr, const void* gaddr) {
    asm volatile("cp.async.cg.shared.global [%0], [%1], 16;" :: "r"(saddr), "l"(gaddr));
}
__device__ __forceinline__ void cp_commit() { asm volatile("cp.async.commit_group;"); }
__device__ __forceinline__ void cp_wait2()  { asm volatile("cp.async.wait_group 2;"); }
__device__ __forceinline__ void cp_wait1()  { asm volatile("cp.async.wait_group 1;"); }
__device__ __forceinline__ void cp_wait0()  { asm volatile("cp.async.wait_group 0;"); }
__device__ __forceinline__ void ldm_x4(uint32_t& r0, uint32_t& r1, uint32_t& r2, uint32_t& r3,
                                       uint32_t addr) {
    asm volatile("ldmatrix.sync.aligned.m8n8.x4.shared.b16 {%0,%1,%2,%3}, [%4];"
                 : "=r"(r0), "=r"(r1), "=r"(r2), "=r"(r3) : "r"(addr));
}
__device__ __forceinline__ void mma16816(float* c, const uint32_t* a, uint32_t b0, uint32_t b1) {
    asm volatile("mma.sync.aligned.m16n8k16.row.col.f32.f16.f16.f32 "
                 "{%0,%1,%2,%3}, {%4,%5,%6,%7}, {%8,%9}, {%0,%1,%2,%3};"
                 : "+f"(c[0]), "+f"(c[1]), "+f"(c[2]), "+f"(c[3])
                 : "r"(a[0]), "r"(a[1]), "r"(a[2]), "r"(a[3]), "r"(b0), "r"(b1));
}
__device__ __forceinline__ uint32_t pk2h(float a, float b) {
    __half2 t = __floats2half2_rn(a, b);
    return *reinterpret_cast<uint32_t*>(&t);
}

// ---------------------------------------------------------------------------
// fp16 HMMA GEMM.  C[m,n] = sum_k A[m,k] * B[n,k]  (row-major, K contiguous)
// BM=128, BN=256, BK=64. 256 threads, warp grid 2(m) x 4(n), warp tile 64x64.
// 3-stage cp.async pipeline. Epilogue modes:
//   0: fp32 C (+bias +resid)      1: fp16 Ch (+bias +relu)
//   2: QKV routing -> q (x0.125), k, v  fp16 head-major [z, s, d]
// ---------------------------------------------------------------------------
__global__ __launch_bounds__(256, 1)
void gemm16(const fp16* __restrict__ A, int lda,
            const fp16* __restrict__ B, int ldb,
            const float* __restrict__ bias, const float* __restrict__ resid,
            float* __restrict__ C, fp16* __restrict__ Ch,
            fp16* __restrict__ qO, fp16* __restrict__ kO, fp16* __restrict__ vO,
            int ldc, int K, int relu, int mode)
{
    extern __shared__ char smem[];
    const uint32_t sbase = smem_u32(smem);
    constexpr int STG = 16384 + 32768;          // A 16KB + B 32KB per stage

    const int tid = threadIdx.x, wid = tid >> 5, lane = tid & 31;
    const int wm = wid >> 2, wn = wid & 3;

    const long m0 = (long)blockIdx.y * 128;
    const long n0 = (long)blockIdx.x * 256;
    const int nt = K >> 6;

    float acc[4][8][4];
#pragma unroll
    for (int i = 0; i < 4; i++)
#pragma unroll
        for (int j = 0; j < 8; j++)
#pragma unroll
            for (int q = 0; q < 4; q++) acc[i][j][q] = 0.f;

    auto load_tile = [&](int i, int st) {
        const long k0 = (long)i << 6;
        const uint32_t S = sbase + st * STG;
#pragma unroll
        for (int it = 0; it < 4; it++) {
            int f = tid + it * 256, r = f >> 3, c = f & 7;
            cp16(S + r * 128 + ((c ^ (r & 7)) << 4),
                 A + (m0 + r) * (long)lda + k0 + c * 8);
        }
#pragma unroll
        for (int it = 0; it < 8; it++) {
            int f = tid + it * 256, r = f >> 3, c = f & 7;
            cp16(S + 16384 + r * 128 + ((c ^ (r & 7)) << 4),
                 B + (n0 + r) * (long)ldb + k0 + c * 8);
        }
        cp_commit();
    };

    load_tile(0, 0);
    load_tile(1, 1);

    for (int i = 0; i < nt; i++) {
        if (i + 2 < nt) load_tile(i + 2, (i + 2) % 3);
        else            cp_commit();            // empty group keeps count uniform
        cp_wait2();
        __syncthreads();

        const uint32_t S = sbase + (i % 3) * STG;
#pragma unroll
        for (int ks = 0; ks < 4; ks++) {
            uint32_t af[4][4];
#pragma unroll
            for (int mi = 0; mi < 4; mi++) {
                int r = wm * 64 + mi * 16 + (lane & 15);
                int c = ks * 2 + (lane >> 4);
                ldm_x4(af[mi][0], af[mi][1], af[mi][2], af[mi][3],
                       S + r * 128 + ((c ^ (r & 7)) << 4));
            }
            uint32_t bfr[8][2];
#pragma unroll
            for (int p = 0; p < 4; p++) {
                int n = wn * 64 + p * 16 + (lane & 7) + ((lane >> 4) << 3);
                int c = ks * 2 + ((lane >> 3) & 1);
                uint32_t r0, r1, r2, r3;
                ldm_x4(r0, r1, r2, r3, S + 16384 + n * 128 + ((c ^ (n & 7)) << 4));
                bfr[2*p][0] = r0; bfr[2*p][1] = r1;
                bfr[2*p+1][0] = r2; bfr[2*p+1][1] = r3;
            }
#pragma unroll
            for (int mi = 0; mi < 4; mi++)
#pragma unroll
                for (int ni = 0; ni < 8; ni++)
                    mma16816(acc[mi][ni], af[mi], bfr[ni][0], bfr[ni][1]);
        }
        __syncthreads();
    }

    const long mw = m0 + wm * 64;
    const long nw = n0 + wn * 64;
#pragma unroll
    for (int mi = 0; mi < 4; mi++) {
#pragma unroll
        for (int ni = 0; ni < 8; ni++) {
            float* c = acc[mi][ni];
            long r0 = mw + mi * 16 + (lane >> 2);
            long cc = nw + ni * 8 + (lane & 3) * 2;
            float2 v0 = make_float2(c[0], c[1]);
            float2 v1 = make_float2(c[2], c[3]);
            if (bias) {
                float2 bv = *reinterpret_cast<const float2*>(bias + cc);
                v0.x += bv.x; v0.y += bv.y; v1.x += bv.x; v1.y += bv.y;
            }
            if (mode == 0) {
                if (resid) {
                    float2 ra = *reinterpret_cast<const float2*>(resid + r0 * ldc + cc);
                    float2 rb = *reinterpret_cast<const float2*>(resid + (r0 + 8) * ldc + cc);
                    v0.x += ra.x; v0.y += ra.y; v1.x += rb.x; v1.y += rb.y;
                }
                *reinterpret_cast<float2*>(C + r0 * ldc + cc) = v0;
                *reinterpret_cast<float2*>(C + (r0 + 8) * ldc + cc) = v1;
            } else if (mode == 1) {
                if (relu) {
                    v0.x = fmaxf(v0.x, 0.f); v0.y = fmaxf(v0.y, 0.f);
                    v1.x = fmaxf(v1.x, 0.f); v1.y = fmaxf(v1.y, 0.f);
                }
                *reinterpret_cast<uint32_t*>(Ch + r0 * ldc + cc) = pk2h(v0.x, v0.y);
                *reinterpret_cast<uint32_t*>(Ch + (r0 + 8) * ldc + cc) = pk2h(v1.x, v1.y);
            } else {
                // QKV routing: row = s*8+b, col selects q/k/v region
                int region = (int)(cc >> 10);
                float sc = (region == 0) ? 0.125f : 1.0f;
                fp16* dst = (region == 0) ? qO : ((region == 1) ? kO : vO);
                int col = (int)cc & 1023;
                int h = col >> 6, d = col & 63;
                int s = (int)(r0 >> 3), b = (int)(r0 & 7);
                long off = (((long)(b * 16 + h)) * 1024 + s) * 64 + d;
                *reinterpret_cast<uint32_t*>(dst + off)      = pk2h(v0.x * sc, v0.y * sc);
                *reinterpret_cast<uint32_t*>(dst + off + 64) = pk2h(v1.x * sc, v1.y * sc);
            }
        }
    }
}

// ---------------------------------------------------------------------------
// Transpose v [z, s, d] -> vt [z, d, t=s], fp16, 64x64 tiles in smem.
// grid (s/64, z), 256 threads.
// ---------------------------------------------------------------------------
__global__ void vtrans(const fp16* __restrict__ vsd, fp16* __restrict__ vt)
{
    __shared__ fp16 t[64][66];
    const int s0 = blockIdx.x * 64;
    const long z = blockIdx.y;
    const int tid = threadIdx.x;
    const fp16* src = vsd + (z * 1024 + s0) * 64;
#pragma unroll
    for (int it = 0; it < 8; it++) {
        int f = tid + it * 256;          // 2048 u32
        int r = f >> 5, c2 = f & 31;     // r = s row, c2 = d pair
        uint32_t v = *reinterpret_cast<const uint32_t*>(src + r * 64 + c2 * 2);
        __half2 h = *reinterpret_cast<__half2*>(&v);
        t[c2 * 2][r]     = __low2half(h);
        t[c2 * 2 + 1][r] = __high2half(h);
    }
    __syncthreads();
    fp16* dst = vt + z * (long)HD * 1024 + s0;
#pragma unroll
    for (int it = 0; it < 8; it++) {
        int f = tid + it * 256;
        int r = f >> 5, c2 = f & 31;     // r = d row, c2 = t pair
        __half2 h = __halves2half2(t[r][c2 * 2], t[r][c2 * 2 + 1]);
        *reinterpret_cast<uint32_t*>(dst + (long)r * 1024 + c2 * 2) =
            *reinterpret_cast<uint32_t*>(&h);
    }
}

// ---------------------------------------------------------------------------
// Fused flash attention (fp16): ctx = softmax(q k^T) v, q pre-scaled.
// CTA = 128 q-rows of one head; 8 warps x 16 rows; online softmax.
// ---------------------------------------------------------------------------
__global__ __launch_bounds__(256, 1)
void flash16(const fp16* __restrict__ qH, const fp16* __restrict__ kH,
             const fp16* __restrict__ vH, fp16* __restrict__ ctx)
{
    extern __shared__ char smem[];
    const uint32_t sb = smem_u32(smem);
    const int tid = threadIdx.x, wid = tid >> 5, lane = tid & 31;
    const int z = blockIdx.y;
    const long qoff = ((long)z * SEQ + (long)blockIdx.x * 128) * HD;
    const long koff = (long)z * SEQ * HD;
    const long voff = (long)z * HD * SEQ;

    const uint32_t Qs = sb, ST = sb + 16384;
    constexpr uint32_t STG = 32768;

#pragma unroll
    for (int it = 0; it < 4; it++) {
        int f = tid + it * 256, r = f >> 3, c = f & 7;
        cp16(Qs + r * 128 + ((c ^ (r & 7)) << 4), qH + qoff + r * 64 + c * 8);
    }
    cp_commit();

    auto load_kv = [&](int t, int st) {
        const long t0 = (long)t * 128;
        const uint32_t B = ST + st * STG;
#pragma unroll
        for (int it = 0; it < 4; it++) {
            int f = tid + it * 256, r = f >> 3, c = f & 7;
            cp16(B + r * 128 + ((c ^ (r & 7)) << 4), kH + koff + (t0 + r) * 64 + c * 8);
        }
#pragma unroll
        for (int it = 0; it < 4; it++) {
            int f = tid + it * 256, r = f >> 4, c = f & 15;
            cp16(B + 16384 + r * 256 + ((c ^ (r & 7)) << 4),
                 vH + voff + (long)r * 1024 + t0 + c * 8);
        }
        cp_commit();
    };

    load_kv(0, 0);
    cp_wait1();
    __syncthreads();

    uint32_t qf[4][4];
#pragma unroll
    for (int ks = 0; ks < 4; ks++) {
        int r = wid * 16 + (lane & 15), c = ks * 2 + (lane >> 4);
        ldm_x4(qf[ks][0], qf[ks][1], qf[ks][2], qf[ks][3],
               Qs + r * 128 + ((c ^ (r & 7)) << 4));
    }

    float S[16][4], O[8][4];
    float m0 = -1e30f, m1 = -1e30f, l0 = 0.f, l1 = 0.f;
#pragma unroll
    for (int i = 0; i < 8; i++)
#pragma unroll
        for (int q = 0; q < 4; q++) O[i][q] = 0.f;

    for (int t = 0; t < 8; t++) {
        const int st = t & 1;
        if (t + 1 < 8) { load_kv(t + 1, st ^ 1); cp_wait1(); }
        else           { cp_wait0(); }
        __syncthreads();

#pragma unroll
        for (int i = 0; i < 16; i++)
#pragma unroll
            for (int q = 0; q < 4; q++) S[i][q] = 0.f;

        const uint32_t B = ST + st * STG;
#pragma unroll
        for (int ks = 0; ks < 4; ks++) {
#pragma unroll
            for (int p = 0; p < 8; p++) {
                int n = p * 16 + (lane & 7) + ((lane >> 4) << 3);
                int c = ks * 2 + ((lane >> 3) & 1);
                uint32_t r0, r1, r2, r3;
                ldm_x4(r0, r1, r2, r3, B + n * 128 + ((c ^ (n & 7)) << 4));
                mma16816(S[2*p],   qf[ks], r0, r1);
                mma16816(S[2*p+1], qf[ks], r2, r3);
            }
        }

        float tm0 = -1e30f, tm1 = -1e30f;
#pragma unroll
        for (int i = 0; i < 16; i++) {
            tm0 = fmaxf(tm0, fmaxf(S[i][0], S[i][1]));
            tm1 = fmaxf(tm1, fmaxf(S[i][2], S[i][3]));
        }
#pragma unroll
        for (int o = 1; o <= 2; o <<= 1) {
            tm0 = fmaxf(tm0, __shfl_xor_sync(~0u, tm0, o));
            tm1 = fmaxf(tm1, __shfl_xor_sync(~0u, tm1, o));
        }
        float nm0 = fmaxf(m0, tm0), nm1 = fmaxf(m1, tm1);
        float sc0 = __expf(m0 - nm0), sc1 = __expf(m1 - nm1);
        m0 = nm0; m1 = nm1;
        float ls0 = 0.f, ls1 = 0.f;
#pragma unroll
        for (int i = 0; i < 16; i++) {
            S[i][0] = __expf(S[i][0] - m0); ls0 += S[i][0];
            S[i][1] = __expf(S[i][1] - m0); ls0 += S[i][1];
            S[i][2] = __expf(S[i][2] - m1); ls1 += S[i][2];
            S[i][3] = __expf(S[i][3] - m1); ls1 += S[i][3];
        }
#pragma unroll
        for (int o = 1; o <= 2; o <<= 1) {
            ls0 += __shfl_xor_sync(~0u, ls0, o);
            ls1 += __shfl_xor_sync(~0u, ls1, o);
        }
        l0 = l0 * sc0 + ls0;
        l1 = l1 * sc1 + ls1;
#pragma unroll
        for (int i = 0; i < 8; i++) {
            O[i][0] *= sc0; O[i][1] *= sc0;
            O[i][2] *= sc1; O[i][3] *= sc1;
        }

#pragma unroll
        for (int j = 0; j < 8; j++) {
            uint32_t ph[4];
            ph[0] = pk2h(S[2*j][0],   S[2*j][1]);
            ph[1] = pk2h(S[2*j][2],   S[2*j][3]);
            ph[2] = pk2h(S[2*j+1][0], S[2*j+1][1]);
            ph[3] = pk2h(S[2*j+1][2], S[2*j+1][3]);
#pragma unroll
            for (int p = 0; p < 4; p++) {
                int n = p * 16 + (lane & 7) + ((lane >> 4) << 3);
                int c = j * 2 + ((lane >> 3) & 1);
                uint32_t r0, r1, r2, r3;
                ldm_x4(r0, r1, r2, r3, B + 16384 + n * 256 + ((c ^ (n & 7)) << 4));
                mma16816(O[2*p],   ph, r0, r1);
                mma16816(O[2*p+1], ph, r2, r3);
            }
        }
        __syncthreads();
    }

    float inv0 = 1.f / l0, inv1 = 1.f / l1;
    long s0 = (long)blockIdx.x * 128 + wid * 16 + (lane >> 2);
    long cb = (long)(z >> 4) * 1024 + (long)(z & 15) * 64;
#pragma unroll
    for (int ni = 0; ni < 8; ni++) {
        long d0 = cb + ni * 8 + (lane & 3) * 2;
        *reinterpret_cast<uint32_t*>(ctx + s0 * 8192 + d0) =
            pk2h(O[ni][0] * inv0, O[ni][1] * inv0);
        *reinterpret_cast<uint32_t*>(ctx + (s0 + 8) * 8192 + d0) =
            pk2h(O[ni][2] * inv1, O[ni][3] * inv1);
    }
}

// ---------------- conversions / LN ------------------------------------------
__global__ void cvt_h(const float* __restrict__ in, fp16* __restrict__ out, long n4)
{
    long i = (long)blockIdx.x * blockDim.x + threadIdx.x;
    if (i >= n4) return;
    float4 v = reinterpret_cast<const float4*>(in)[i];
    uint2 o;
    o.x = pk2h(v.x, v.y);
    o.y = pk2h(v.z, v.w);
    reinterpret_cast<uint2*>(out)[i] = o;
}

__global__ void layernorm_kernel(const float* __restrict__ in, const float* __restrict__ g,
                                 const float* __restrict__ b, float* __restrict__ out,
                                 fp16* __restrict__ out_h)
{
    __shared__ float rs[8], rq[8];
    const long row = blockIdx.x;
    const int tid = threadIdx.x;
    float4 x = reinterpret_cast<const float4*>(in + row * (long)DM)[tid];
    float s = x.x + x.y + x.z + x.w;
    float q = x.x*x.x + x.y*x.y + x.z*x.z + x.w*x.w;
#pragma unroll
    for (int o = 16; o > 0; o >>= 1) {
        s += __shfl_xor_sync(~0u, s, o);
        q += __shfl_xor_sync(~0u, q, o);
    }
    if ((tid & 31) == 0) { rs[tid >> 5] = s; rq[tid >> 5] = q; }
    __syncthreads();
    float ts = 0.f, tq = 0.f;
#pragma unroll
    for (int i = 0; i < 8; i++) { ts += rs[i]; tq += rq[i]; }
    const float mu = ts * (1.f / DM);
    const float var = tq * (1.f / DM) - mu * mu;
    const float r = rsqrtf(var + EPS);
    float4 gg = reinterpret_cast<const float4*>(g)[tid];
    float4 bb = reinterpret_cast<const float4*>(b)[tid];
    float4 y;
    y.x = (x.x - mu) * r * gg.x + bb.x;
    y.y = (x.y - mu) * r * gg.y + bb.y;
    y.z = (x.z - mu) * r * gg.z + bb.z;
    y.w = (x.w - mu) * r * gg.w + bb.w;
    if (out)
        reinterpret_cast<float4*>(out + row * (long)DM)[tid] = y;
    if (out_h) {
        uint2 o;
        o.x = pk2h(y.x, y.y);
        o.y = pk2h(y.z, y.w);
        reinterpret_cast<uint2*>(out_h + row * (long)DM)[tid] = o;
    }
}

// ---------------- host ------------------------------------------------------
#define SYMADDR(p, s) do { void* v_; cudaGetSymbolAddress(&v_, s); p = (decltype(p))v_; } while (0)

extern "C" void kernel_launch(void* const* d_in, const int* in_sizes, int n_in,
                              void* d_out, int out_size)
{
    (void)in_sizes; (void)n_in; (void)out_size;
    const float* src = (const float*)d_in[0];
    const float* in_proj_w = (const float*)d_in[1];
    const float* in_proj_b = (const float*)d_in[2];
    const float* out_w = (const float*)d_in[3];
    const float* out_b = (const float*)d_in[4];
    const float* w1 = (const float*)d_in[5];
    const float* b1 = (const float*)d_in[6];
    const float* w2 = (const float*)d_in[7];
    const float* b2 = (const float*)d_in[8];
    const float* g1 = (const float*)d_in[9];
    const float* be1 = (const float*)d_in[10];
    const float* g2 = (const float*)d_in[11];
    const float* be2 = (const float*)d_in[12];
    float* out = (float*)d_out;

    float *p_x, *p_tmp;
    fp16 *srcH, *wiH, *owH, *w1H, *w2H, *qH, *kH, *vsd, *vtH, *ctxH, *xH, *h1H;
    SYMADDR(p_x, g_x); SYMADDR(p_tmp, g_tmp);
    SYMADDR(srcH, g_srcH); SYMADDR(wiH, g_wiH); SYMADDR(owH, g_owH);
    SYMADDR(w1H, g_w1H); SYMADDR(w2H, g_w2H);
    SYMADDR(qH, g_qH); SYMADDR(kH, g_kH); SYMADDR(vsd, g_vsd); SYMADDR(vtH, g_vtH);
    SYMADDR(ctxH, g_ctxH); SYMADDR(xH, g_xH); SYMADDR(h1H, g_h1H);

    const int GSM  = 3 * (16384 + 32768);   // 144 KB, 3 stages
    const int FASM = 16384 + 2 * 32768;     // 80 KB
    cudaFuncSetAttribute(gemm16, cudaFuncAttributeMaxDynamicSharedMemorySize, GSM);
    cudaFuncSetAttribute(flash16, cudaFuncAttributeMaxDynamicSharedMemorySize, FASM);

    auto cvt = [](const float* in, fp16* o, long n) {
        long n4 = n >> 2;
        cvt_h<<<(unsigned)((n4 + 255) / 256), 256>>>(in, o, n4);
    };

    // fp16 conversions of inputs
    cvt(src, srcH, (long)SB * DM);
    cvt(in_proj_w, wiH, (long)3 * DM * DM);
    cvt(out_w, owH, (long)DM * DM);
    cvt(w1, w1H, (long)FF * DM);
    cvt(w2, w2H, (long)DM * FF);

    // 1) QKV GEMM -> q/k/v fp16 head-major directly (mode 2)
    gemm16<<<dim3(12, 64), 256, GSM>>>(srcH, DM, wiH, DM,
                                       in_proj_b, nullptr, nullptr, nullptr,
                                       qH, kH, vsd, 0, DM, 0, 2);

    // 2) v transpose [z,s,d] -> [z,d,t]
    vtrans<<<dim3(16, BATCH * NH), 256>>>(vsd, vtH);

    // 3) fused attention -> ctx fp16
    flash16<<<dim3(8, BATCH * NH), 256, FASM>>>(qH, kH, vtH, ctxH);

    // 4) tmp = ctx @ out_w^T + out_b + src ; x = LN1 (fp32 + fp16)
    gemm16<<<dim3(4, 64), 256, GSM>>>(ctxH, DM, owH, DM,
                                      out_b, src, p_tmp, nullptr,
                                      nullptr, nullptr, nullptr, DM, DM, 0, 0);
    layernorm_kernel<<<SB, 256>>>(p_tmp, g1, be1, p_x, xH);

    // 5) FFN1: h1 = relu(x @ w1^T + b1) -> fp16
    gemm16<<<dim3(16, 64), 256, GSM>>>(xH, DM, w1H, DM,
                                       b1, nullptr, nullptr, h1H,
                                       nullptr, nullptr, nullptr, FF, DM, 1, 1);

    // 6) FFN2: tmp = h1 @ w2^T + b2 + x
    gemm16<<<dim3(4, 64), 256, GSM>>>(h1H, FF, w2H, FF,
                                      b2, p_x, p_tmp, nullptr,
                                      nullptr, nullptr, nullptr, DM, FF, 0, 0);

    // 7) out = LN2
    layernorm_kernel<<<SB, 256>>>(p_tmp, g2, be2, out, nullptr);
}